// round 11
// baseline (speedup 1.0000x reference)
#include <cuda_runtime.h>
#include <cuda_fp16.h>
#include <cstdint>

// ---------------- problem dims ----------------
#define BATCH_SZ 16384
#define IN_F     2048
#define OUT_F    2048
#define NSEG     6
#define KTOT     (IN_F * NSEG)   // 12288

// ---------------- GEMM tiling ----------------
#define BM 128
#define BN 128
#define BK 64
#define STAGES 3
#define KITERS (KTOT / BK)       // 192 (divisible by 3)
#define NTHREADS 256             // 8 warps; 2 CTAs/SM

#define LDS_STRIDE 72                        // halves per smem row (64 data + 8 pad)
#define A_STG_HALVES (BM * LDS_STRIDE)       // 9216
#define B_STG_HALVES (BN * LDS_STRIDE)       // 9216
#define SMEM_BYTES ((STAGES * (A_STG_HALVES + B_STG_HALVES)) * 2)  // 110592

// prep kernel block split
#define EXPAND_BLOCKS (BATCH_SZ * IN_F / 8 / 256)   // 16384
#define WPACK_BLOCKS  (OUT_F * IN_F / 4 / 256)      // 4096

// ---------------- scratch (device globals; no alloc allowed) ----------------
static __device__ __align__(1024) __half g_Apack[(size_t)BATCH_SZ * KTOT]; // 402 MB
static __device__ __align__(1024) __half g_Wpack[(size_t)OUT_F * KTOT];   // 50 MB

// ---------------- helpers ----------------
__device__ __forceinline__ uint32_t smem_u32(const void* p) {
    uint32_t a;
    asm("{ .reg .u64 t; cvta.to.shared.u64 t, %1; cvt.u32.u64 %0, t; }" : "=r"(a) : "l"(p));
    return a;
}
__device__ __forceinline__ void cp16(uint32_t saddr, const void* g) {
    asm volatile("cp.async.cg.shared.global [%0], [%1], 16;" :: "r"(saddr), "l"(g) : "memory");
}
__device__ __forceinline__ void cp_commit() {
    asm volatile("cp.async.commit_group;" ::: "memory");
}
template <int N>
__device__ __forceinline__ void cp_wait() {
    asm volatile("cp.async.wait_group %0;" :: "n"(N) : "memory");
}
__device__ __forceinline__ void ldsm4(uint32_t* r, uint32_t addr) {
    asm volatile("ldmatrix.sync.aligned.m8n8.x4.shared.b16 {%0,%1,%2,%3}, [%4];"
                 : "=r"(r[0]), "=r"(r[1]), "=r"(r[2]), "=r"(r[3]) : "r"(addr));
}
__device__ __forceinline__ void mma16816(float* c, const uint32_t* a, uint32_t b0, uint32_t b1) {
    asm volatile(
        "mma.sync.aligned.m16n8k16.row.col.f32.f16.f16.f32 "
        "{%0,%1,%2,%3}, {%4,%5,%6,%7}, {%8,%9}, {%0,%1,%2,%3};"
        : "+f"(c[0]), "+f"(c[1]), "+f"(c[2]), "+f"(c[3])
        : "r"(a[0]), "r"(a[1]), "r"(a[2]), "r"(a[3]), "r"(b0), "r"(b1));
}

// ---------------- kernel 1: merged prep (A expansion + weight pack) -----------------
__global__ void __launch_bounds__(256) prep_kernel(const float* __restrict__ x,
                                                   const float* __restrict__ bw,
                                                   const float* __restrict__ sw,
                                                   __half* __restrict__ A,
                                                   __half* __restrict__ W) {
    if (blockIdx.x < EXPAND_BLOCKS) {
        int idx = blockIdx.x * blockDim.x + threadIdx.x;
        int b = idx >> 8;
        int i = (idx & 255) << 3;
        const float* xp = x + (size_t)b * IN_F + i;
        float4 xv0 = *reinterpret_cast<const float4*>(xp);
        float4 xv1 = *reinterpret_cast<const float4*>(xp + 4);
        float xs[8] = {xv0.x, xv0.y, xv0.z, xv0.w, xv1.x, xv1.y, xv1.z, xv1.w};

        const float C0 = 42.521082f;    // exp( 3.75)
        const float C1 = 3.4903430f;    // exp( 1.25)
        const float C2 = 0.28650480f;   // exp(-1.25)
        const float C3 = 0.023517746f;  // exp(-3.75)

        __half2 seg[NSEG][4];
#pragma unroll
        for (int p = 0; p < 4; p++) {
            float v0[NSEG], v1[NSEG];
#pragma unroll
            for (int h = 0; h < 2; h++) {
                float a0 = xs[2 * p + h];
                float s  = a0 / (1.f + __expf(-a0));
                float u  = __expf(5.f * a0);
                float d  = a0 + 1.f;
                float bb = __expf(-5.f * d * d);
                float* v = h ? v1 : v0;
                v[0] = s;
                v[1] = bb;
                bb *= u * C0; v[2] = bb;
                bb *= u * C1; v[3] = bb;
                bb *= u * C2; v[4] = bb;
                bb *= u * C3; v[5] = bb;
            }
#pragma unroll
            for (int s2 = 0; s2 < NSEG; s2++)
                seg[s2][p] = __floats2half2_rn(v0[s2], v1[s2]);
        }
        __half* Ab = A + (size_t)b * KTOT + i;
#pragma unroll
        for (int s2 = 0; s2 < NSEG; s2++) {
            float4 v;
            v.x = __uint_as_float(*reinterpret_cast<uint32_t*>(&seg[s2][0]));
            v.y = __uint_as_float(*reinterpret_cast<uint32_t*>(&seg[s2][1]));
            v.z = __uint_as_float(*reinterpret_cast<uint32_t*>(&seg[s2][2]));
            v.w = __uint_as_float(*reinterpret_cast<uint32_t*>(&seg[s2][3]));
            __stcs(reinterpret_cast<float4*>(Ab + s2 * IN_F), v);   // streaming 16B store
        }
    } else {
        int t = (blockIdx.x - EXPAND_BLOCKS) * blockDim.x + threadIdx.x;
        int o = t >> 9;
        int i = (t & 511) << 2;
        int base = o * IN_F + i;

        float4 b4 = *reinterpret_cast<const float4*>(bw + base);
        __half2 h0 = __floats2half2_rn(b4.x, b4.y);
        __half2 h1 = __floats2half2_rn(b4.z, b4.w);
        __half* Wo = W + (size_t)o * KTOT + i;
        uint2 bw8;
        bw8.x = *reinterpret_cast<uint32_t*>(&h0);
        bw8.y = *reinterpret_cast<uint32_t*>(&h1);
        __stcs(reinterpret_cast<uint2*>(Wo), bw8);                  // 8B store

        float s[20];
        const float* sp = sw + (size_t)base * 5;
#pragma unroll
        for (int j = 0; j < 20; j += 4) {
            float4 v = *reinterpret_cast<const float4*>(sp + j);
            s[j] = v.x; s[j + 1] = v.y; s[j + 2] = v.z; s[j + 3] = v.w;
        }
#pragma unroll
        for (int g = 0; g < 5; g++) {
            __half2 g0 = __floats2half2_rn(s[0 * 5 + g], s[1 * 5 + g]);
            __half2 g1 = __floats2half2_rn(s[2 * 5 + g], s[3 * 5 + g]);
            uint2 sw8;
            sw8.x = *reinterpret_cast<uint32_t*>(&g0);
            sw8.y = *reinterpret_cast<uint32_t*>(&g1);
            __stcs(reinterpret_cast<uint2*>(Wo + (size_t)(g + 1) * IN_F), sw8);
        }
    }
}

// ---------------- kernel 2: mma.sync GEMM, 2 CTAs/SM, ks rotation + bf dbuf ---------
__global__ void __launch_bounds__(NTHREADS, 2)
gemm_kernel(const __half* __restrict__ A, const __half* __restrict__ B,
            float* __restrict__ out) {
    extern __shared__ char smem_raw[];
    const uint32_t smemA = smem_u32(smem_raw);
    const uint32_t smemB = smemA + STAGES * A_STG_HALVES * 2;

    const int tid = threadIdx.x;
    const int w = tid >> 5, l = tid & 31;
    const int wm = (w >> 2) * 64;           // 2 warp-rows
    const int wn = (w & 3) * 32;            // 4 warp-cols
    const int rot = (w & 1) * 2;            // per-warp ks rotation (burst decorrelation)
    const int ntile = blockIdx.x, mtile = blockIdx.y;

    const __half* gA = A + (size_t)(mtile * BM) * KTOT;
    const __half* gB = B + (size_t)(ntile * BN) * KTOT;

    const uint32_t a_lane = (uint32_t)((wm + (l & 15)) * LDS_STRIDE + (l >> 4) * 8);
    const uint32_t b_lane = (uint32_t)((wn + (l & 15)) * LDS_STRIDE + (l >> 4) * 8);

    // per-thread cp.async coordinates
    const int ld_row = tid >> 3;            // 0..31 (+32 per r)
    const int ld_ch  = (tid & 7) * 8;       // halves

    float acc[4][4][4];
#pragma unroll
    for (int mi = 0; mi < 4; mi++)
#pragma unroll
        for (int j = 0; j < 4; j++)
#pragma unroll
            for (int q = 0; q < 4; q++) acc[mi][j][q] = 0.f;

    auto load_A = [&](int slot, int kc) {
#pragma unroll
        for (int r = 0; r < 4; r++) {
            int row = ld_row + r * 32;
            uint32_t sa = smemA + (uint32_t)(slot * A_STG_HALVES + row * LDS_STRIDE + ld_ch) * 2;
            cp16(sa, gA + (size_t)row * KTOT + kc * BK + ld_ch);
        }
    };
    auto load_B2 = [&](int slot, int kc, int half) {    // half = 0 or 1 (2 rows each)
#pragma unroll
        for (int r = 0; r < 2; r++) {
            int row = ld_row + (half * 2 + r) * 32;
            uint32_t sb = smemB + (uint32_t)(slot * B_STG_HALVES + row * LDS_STRIDE + ld_ch) * 2;
            cp16(sb, gB + (size_t)row * KTOT + kc * BK + ld_ch);
        }
    };
    auto load_full = [&](int slot, int kc) {
        load_A(slot, kc);
        load_B2(slot, kc, 0);
        load_B2(slot, kc, 1);
    };

    // prologue: prefetch 2 stages
    load_full(0, 0); cp_commit();
    load_full(1, 1); cp_commit();

    // body: kc unrolled by STAGES(3); slots compile-time; ks rotated per warp
    auto body = [&](int kc, int slot, int nslot) {
        const uint32_t aB = smemA + (uint32_t)(slot * A_STG_HALVES) * 2 + a_lane * 2;
        const uint32_t bB = smemB + (uint32_t)(slot * B_STG_HALVES) * 2 + b_lane * 2;

        cp_wait<1>();
        __syncthreads();

        const int nk = kc + 2;
        const bool doload = nk < KITERS;

        uint32_t bfb[2][2][4];            // double-buffered B fragments
        // prefetch B frags for the warp's first (rotated) ks
#pragma unroll
        for (int ni = 0; ni < 2; ni++)
            ldsm4(bfb[0][ni], bB + (uint32_t)(ni * 16 * LDS_STRIDE + rot * 16) * 2);

#pragma unroll
        for (int ks = 0; ks < 4; ks++) {
            const int ksx = (ks + rot) & 3;           // this warp's actual k-step
            const int cur = ks & 1, nxt = cur ^ 1;

            uint32_t af[4][4];
#pragma unroll
            for (int mi = 0; mi < 4; mi++)
                ldsm4(af[mi], aB + (uint32_t)(mi * 16 * LDS_STRIDE + ksx * 16) * 2);

            if (ks < 3) {                              // prefetch next ks's B frags
                const int ksn = (ks + 1 + rot) & 3;
#pragma unroll
                for (int ni = 0; ni < 2; ni++)
                    ldsm4(bfb[nxt][ni], bB + (uint32_t)(ni * 16 * LDS_STRIDE + ksn * 16) * 2);
            }

#pragma unroll
            for (int mi = 0; mi < 4; mi++) {
#pragma unroll
                for (int ni = 0; ni < 2; ni++) {
                    mma16816(acc[mi][2 * ni],     af[mi], bfb[cur][ni][0], bfb[cur][ni][2]);
                    mma16816(acc[mi][2 * ni + 1], af[mi], bfb[cur][ni][1], bfb[cur][ni][3]);
                }
            }
            // spread next-stage cp.async between mma chunks
            if (ks == 0 && doload) load_A(nslot, nk);
            if (ks == 1 && doload) load_B2(nslot, nk, 0);
            if (ks == 2) {
                if (doload) load_B2(nslot, nk, 1);
                cp_commit();            // exactly one group per kc
            }
        }
    };

#pragma unroll 1
    for (int kc = 0; kc < KITERS; kc += 3) {
        body(kc + 0, 0, 2);
        body(kc + 1, 1, 0);
        body(kc + 2, 2, 1);
    }

    // epilogue: regs -> gmem
#pragma unroll
    for (int mi = 0; mi < 4; mi++) {
        int row = mtile * BM + wm + mi * 16 + (l >> 2);
        float* orow = out + (size_t)row * OUT_F + ntile * BN + wn + (l & 3) * 2;
#pragma unroll
        for (int j = 0; j < 4; j++) {
            *reinterpret_cast<float2*>(orow + j * 8) =
                make_float2(acc[mi][j][0], acc[mi][j][1]);
            *reinterpret_cast<float2*>(orow + j * 8 + 8 * OUT_F) =
                make_float2(acc[mi][j][2], acc[mi][j][3]);
        }
    }
}

// ---------------- host launch ----------------
extern "C" void kernel_launch(void* const* d_in, const int* in_sizes, int n_in,
                              void* d_out, int out_size) {
    (void)in_sizes; (void)n_in; (void)out_size;
    const float* x  = (const float*)d_in[0];
    const float* bw = (const float*)d_in[1];
    const float* sw = (const float*)d_in[2];
    float* out = (float*)d_out;

    void *aptr = nullptr, *wptr = nullptr;
    cudaGetSymbolAddress(&aptr, g_Apack);
    cudaGetSymbolAddress(&wptr, g_Wpack);

    prep_kernel<<<EXPAND_BLOCKS + WPACK_BLOCKS, 256>>>(x, bw, sw,
                                                       (__half*)aptr, (__half*)wptr);

    cudaFuncSetAttribute(gemm_kernel, cudaFuncAttributeMaxDynamicSharedMemorySize, SMEM_BYTES);
    gemm_kernel<<<dim3(OUT_F / BN, BATCH_SZ / BM), NTHREADS, SMEM_BYTES>>>(
        (const __half*)aptr, (const __half*)wptr, out);
}

// round 12
// speedup vs baseline: 1.0304x; 1.0304x over previous
#include <cuda_runtime.h>
#include <cuda_fp16.h>
#include <cstdint>

// ---------------- problem dims ----------------
#define BATCH_SZ 16384
#define IN_F     2048
#define OUT_F    2048
#define NSEG     6
#define KTOT     (IN_F * NSEG)   // 12288

// ---------------- GEMM tiling ----------------
#define BM 128
#define BN 128
#define BK 64
#define STAGES 3
#define KITERS (KTOT / BK)       // 192 (divisible by 3)
#define NTHREADS 128             // 4 warps (64x64 tiles); 2 CTAs/SM

#define LDS_STRIDE 72                        // halves per smem row (64 data + 8 pad)
#define A_STG_HALVES (BM * LDS_STRIDE)       // 9216
#define B_STG_HALVES (BN * LDS_STRIDE)       // 9216
#define SMEM_BYTES ((STAGES * (A_STG_HALVES + B_STG_HALVES)) * 2)  // 110592

// prep kernel block split
#define EXPAND_BLOCKS (BATCH_SZ * IN_F / 8 / 256)   // 16384
#define WPACK_BLOCKS  (OUT_F * IN_F / 4 / 256)      // 4096

// ---------------- scratch (device globals; no alloc allowed) ----------------
static __device__ __align__(1024) __half g_Apack[(size_t)BATCH_SZ * KTOT]; // 402 MB
static __device__ __align__(1024) __half g_Wpack[(size_t)OUT_F * KTOT];   // 50 MB

// ---------------- helpers ----------------
__device__ __forceinline__ uint32_t smem_u32(const void* p) {
    uint32_t a;
    asm("{ .reg .u64 t; cvta.to.shared.u64 t, %1; cvt.u32.u64 %0, t; }" : "=r"(a) : "l"(p));
    return a;
}
__device__ __forceinline__ void cp16(uint32_t saddr, const void* g) {
    asm volatile("cp.async.cg.shared.global [%0], [%1], 16;" :: "r"(saddr), "l"(g) : "memory");
}
__device__ __forceinline__ void cp_commit() {
    asm volatile("cp.async.commit_group;" ::: "memory");
}
template <int N>
__device__ __forceinline__ void cp_wait() {
    asm volatile("cp.async.wait_group %0;" :: "n"(N) : "memory");
}
__device__ __forceinline__ void ldsm4(uint32_t* r, uint32_t addr) {
    asm volatile("ldmatrix.sync.aligned.m8n8.x4.shared.b16 {%0,%1,%2,%3}, [%4];"
                 : "=r"(r[0]), "=r"(r[1]), "=r"(r[2]), "=r"(r[3]) : "r"(addr));
}
__device__ __forceinline__ void mma16816(float* c, const uint32_t* a, uint32_t b0, uint32_t b1) {
    asm volatile(
        "mma.sync.aligned.m16n8k16.row.col.f32.f16.f16.f32 "
        "{%0,%1,%2,%3}, {%4,%5,%6,%7}, {%8,%9}, {%0,%1,%2,%3};"
        : "+f"(c[0]), "+f"(c[1]), "+f"(c[2]), "+f"(c[3])
        : "r"(a[0]), "r"(a[1]), "r"(a[2]), "r"(a[3]), "r"(b0), "r"(b1));
}

// ---------------- kernel 1: merged prep (A expansion + weight pack) -----------------
__global__ void __launch_bounds__(256) prep_kernel(const float* __restrict__ x,
                                                   const float* __restrict__ bw,
                                                   const float* __restrict__ sw,
                                                   __half* __restrict__ A,
                                                   __half* __restrict__ W) {
    if (blockIdx.x < EXPAND_BLOCKS) {
        int idx = blockIdx.x * blockDim.x + threadIdx.x;
        int b = idx >> 8;
        int i = (idx & 255) << 3;
        const float* xp = x + (size_t)b * IN_F + i;
        float4 xv0 = *reinterpret_cast<const float4*>(xp);
        float4 xv1 = *reinterpret_cast<const float4*>(xp + 4);
        float xs[8] = {xv0.x, xv0.y, xv0.z, xv0.w, xv1.x, xv1.y, xv1.z, xv1.w};

        const float C0 = 42.521082f;    // exp( 3.75)
        const float C1 = 3.4903430f;    // exp( 1.25)
        const float C2 = 0.28650480f;   // exp(-1.25)
        const float C3 = 0.023517746f;  // exp(-3.75)

        __half2 seg[NSEG][4];
#pragma unroll
        for (int p = 0; p < 4; p++) {
            float v0[NSEG], v1[NSEG];
#pragma unroll
            for (int h = 0; h < 2; h++) {
                float a0 = xs[2 * p + h];
                float s  = a0 / (1.f + __expf(-a0));
                float u  = __expf(5.f * a0);
                float d  = a0 + 1.f;
                float bb = __expf(-5.f * d * d);
                float* v = h ? v1 : v0;
                v[0] = s;
                v[1] = bb;
                bb *= u * C0; v[2] = bb;
                bb *= u * C1; v[3] = bb;
                bb *= u * C2; v[4] = bb;
                bb *= u * C3; v[5] = bb;
            }
#pragma unroll
            for (int s2 = 0; s2 < NSEG; s2++)
                seg[s2][p] = __floats2half2_rn(v0[s2], v1[s2]);
        }
        __half* Ab = A + (size_t)b * KTOT + i;
#pragma unroll
        for (int s2 = 0; s2 < NSEG; s2++) {
            float4 v;
            v.x = __uint_as_float(*reinterpret_cast<uint32_t*>(&seg[s2][0]));
            v.y = __uint_as_float(*reinterpret_cast<uint32_t*>(&seg[s2][1]));
            v.z = __uint_as_float(*reinterpret_cast<uint32_t*>(&seg[s2][2]));
            v.w = __uint_as_float(*reinterpret_cast<uint32_t*>(&seg[s2][3]));
            __stcs(reinterpret_cast<float4*>(Ab + s2 * IN_F), v);   // streaming 16B store
        }
    } else {
        int t = (blockIdx.x - EXPAND_BLOCKS) * blockDim.x + threadIdx.x;
        int o = t >> 9;
        int i = (t & 511) << 2;
        int base = o * IN_F + i;

        float4 b4 = *reinterpret_cast<const float4*>(bw + base);
        __half2 h0 = __floats2half2_rn(b4.x, b4.y);
        __half2 h1 = __floats2half2_rn(b4.z, b4.w);
        __half* Wo = W + (size_t)o * KTOT + i;
        uint2 bw8;
        bw8.x = *reinterpret_cast<uint32_t*>(&h0);
        bw8.y = *reinterpret_cast<uint32_t*>(&h1);
        __stcs(reinterpret_cast<uint2*>(Wo), bw8);                  // 8B store

        float s[20];
        const float* sp = sw + (size_t)base * 5;
#pragma unroll
        for (int j = 0; j < 20; j += 4) {
            float4 v = *reinterpret_cast<const float4*>(sp + j);
            s[j] = v.x; s[j + 1] = v.y; s[j + 2] = v.z; s[j + 3] = v.w;
        }
#pragma unroll
        for (int g = 0; g < 5; g++) {
            __half2 g0 = __floats2half2_rn(s[0 * 5 + g], s[1 * 5 + g]);
            __half2 g1 = __floats2half2_rn(s[2 * 5 + g], s[3 * 5 + g]);
            uint2 sw8;
            sw8.x = *reinterpret_cast<uint32_t*>(&g0);
            sw8.y = *reinterpret_cast<uint32_t*>(&g1);
            __stcs(reinterpret_cast<uint2*>(Wo + (size_t)(g + 1) * IN_F), sw8);
        }
    }
}

// ---------------- kernel 2: mma.sync GEMM, 2 CTAs/SM, 4 warps x 64x64 tiles ---------
__global__ void __launch_bounds__(NTHREADS, 2)
gemm_kernel(const __half* __restrict__ A, const __half* __restrict__ B,
            float* __restrict__ out) {
    extern __shared__ char smem_raw[];
    const uint32_t smemA = smem_u32(smem_raw);
    const uint32_t smemB = smemA + STAGES * A_STG_HALVES * 2;

    const int tid = threadIdx.x;
    const int w = tid >> 5, l = tid & 31;
    const int wm = (w >> 1) * 64;           // 2 warp-rows
    const int wn = (w & 1) * 64;            // 2 warp-cols
    const int ntile = blockIdx.x, mtile = blockIdx.y;

    const __half* gA = A + (size_t)(mtile * BM) * KTOT;
    const __half* gB = B + (size_t)(ntile * BN) * KTOT;

    const uint32_t a_lane = (uint32_t)((wm + (l & 15)) * LDS_STRIDE + (l >> 4) * 8);
    const uint32_t b_lane = (uint32_t)((wn + (l & 15)) * LDS_STRIDE + (l >> 4) * 8);

    // per-thread cp.async coordinates (128 threads)
    const int ld_row = tid >> 3;            // 0..15 (+16 per r)
    const int ld_ch  = (tid & 7) * 8;       // halves

    float acc[4][8][4];
#pragma unroll
    for (int mi = 0; mi < 4; mi++)
#pragma unroll
        for (int j = 0; j < 8; j++)
#pragma unroll
            for (int q = 0; q < 4; q++) acc[mi][j][q] = 0.f;

    // quarter-loads: q = 0,1 -> A rows [q*64, q*64+64); q = 2,3 -> B rows likewise
    auto load_q = [&](int slot, int kc, int q) {
        const bool isA = q < 2;
        const int rbase = (q & 1) * 64;
        const uint32_t sbase = isA ? smemA + (uint32_t)(slot * A_STG_HALVES) * 2
                                   : smemB + (uint32_t)(slot * B_STG_HALVES) * 2;
        const __half* g = isA ? gA : gB;
#pragma unroll
        for (int r = 0; r < 4; r++) {
            int row = rbase + ld_row + r * 16;
            uint32_t sa = sbase + (uint32_t)(row * LDS_STRIDE + ld_ch) * 2;
            cp16(sa, g + (size_t)row * KTOT + kc * BK + ld_ch);
        }
    };
    auto load_full = [&](int slot, int kc) {
#pragma unroll
        for (int q = 0; q < 4; q++) load_q(slot, kc, q);
    };

    // prologue: prefetch 2 stages
    load_full(0, 0); cp_commit();
    load_full(1, 1); cp_commit();

    // body: kc unrolled by STAGES(3); slots compile-time; loads spread across ks
    auto body = [&](int kc, int slot, int nslot) {
        const uint32_t aB = smemA + (uint32_t)(slot * A_STG_HALVES) * 2 + a_lane * 2;
        const uint32_t bB = smemB + (uint32_t)(slot * B_STG_HALVES) * 2 + b_lane * 2;

        cp_wait<1>();
        __syncthreads();

        const int nk = kc + 2;
        const bool doload = nk < KITERS;

#pragma unroll
        for (int ks = 0; ks < 4; ks++) {
            uint32_t af[4][4], bf[4][4];
#pragma unroll
            for (int mi = 0; mi < 4; mi++)
                ldsm4(af[mi], aB + (uint32_t)(mi * 16 * LDS_STRIDE + ks * 16) * 2);
#pragma unroll
            for (int ni = 0; ni < 4; ni++)
                ldsm4(bf[ni], bB + (uint32_t)(ni * 16 * LDS_STRIDE + ks * 16) * 2);
#pragma unroll
            for (int mi = 0; mi < 4; mi++) {
#pragma unroll
                for (int ni = 0; ni < 4; ni++) {
                    mma16816(acc[mi][2 * ni],     af[mi], bf[ni][0], bf[ni][2]);
                    mma16816(acc[mi][2 * ni + 1], af[mi], bf[ni][1], bf[ni][3]);
                }
            }
            // spread next-stage cp.async: one quarter per ks step
            if (doload) load_q(nslot, nk, ks);
            if (ks == 3) cp_commit();   // exactly one group per kc
        }
    };

#pragma unroll 1
    for (int kc = 0; kc < KITERS; kc += 3) {
        body(kc + 0, 0, 2);
        body(kc + 1, 1, 0);
        body(kc + 2, 2, 1);
    }

    // epilogue: regs -> gmem
#pragma unroll
    for (int mi = 0; mi < 4; mi++) {
        int row = mtile * BM + wm + mi * 16 + (l >> 2);
        float* orow = out + (size_t)row * OUT_F + ntile * BN + wn + (l & 3) * 2;
#pragma unroll
        for (int j = 0; j < 8; j++) {
            *reinterpret_cast<float2*>(orow + j * 8) =
                make_float2(acc[mi][j][0], acc[mi][j][1]);
            *reinterpret_cast<float2*>(orow + j * 8 + 8 * OUT_F) =
                make_float2(acc[mi][j][2], acc[mi][j][3]);
        }
    }
}

// ---------------- host launch ----------------
extern "C" void kernel_launch(void* const* d_in, const int* in_sizes, int n_in,
                              void* d_out, int out_size) {
    (void)in_sizes; (void)n_in; (void)out_size;
    const float* x  = (const float*)d_in[0];
    const float* bw = (const float*)d_in[1];
    const float* sw = (const float*)d_in[2];
    float* out = (float*)d_out;

    void *aptr = nullptr, *wptr = nullptr;
    cudaGetSymbolAddress(&aptr, g_Apack);
    cudaGetSymbolAddress(&wptr, g_Wpack);

    prep_kernel<<<EXPAND_BLOCKS + WPACK_BLOCKS, 256>>>(x, bw, sw,
                                                       (__half*)aptr, (__half*)wptr);

    cudaFuncSetAttribute(gemm_kernel, cudaFuncAttributeMaxDynamicSharedMemorySize, SMEM_BYTES);
    gemm_kernel<<<dim3(OUT_F / BN, BATCH_SZ / BM), NTHREADS, SMEM_BYTES>>>(
        (const __half*)aptr, (const __half*)wptr, out);
}